// round 2
// baseline (speedup 1.0000x reference)
#include <cuda_runtime.h>
#include <math.h>

#define NBATCH 64
#define NSTEP  128
#define MEMD   128
#define NSLOT  20
#define HSLOT  10
#define NCTA   128
#define OUTC   160

__device__ float g_S [NBATCH * NSTEP * MEMD];
__device__ float g_O [NBATCH * NSTEP * OUTC];
__device__ float g_WK[OUTC * MEMD];
__device__ float g_BK[OUTC];
__device__ float g_VK[NSLOT * MEMD];
__device__ float g_part[2][NCTA][16];
__device__ float g_H [NBATCH * NSLOT * MEMD];
__device__ unsigned g_cnt;
__device__ unsigned g_gen;

__device__ __forceinline__ void ffma2(unsigned long long &acc, unsigned long long a,
                                      unsigned long long b) {
    asm("fma.rn.f32x2 %0, %1, %2, %0;" : "+l"(acc) : "l"(a), "l"(b));
}
__device__ __forceinline__ unsigned long long pack2(float x) {
    unsigned long long r; asm("mov.b64 %0, {%1, %1};" : "=l"(r) : "f"(x)); return r;
}
__device__ __forceinline__ float2 up2(unsigned long long v) {
    float2 r; asm("mov.b64 {%0, %1}, %2;" : "=f"(r.x), "=f"(r.y) : "l"(v)); return r;
}

__global__ void k_setup(const float* __restrict__ Ww, const float* __restrict__ Wb,
                        const float* __restrict__ sk, const float* __restrict__ Vw,
                        const float* __restrict__ Vb) {
    int bid = blockIdx.x, tid = threadIdx.x;
    if (bid < NSLOT) {
        float acc = Vb[tid];
        const float* skr = sk + bid * MEMD;
        const float* vwr = Vw + tid * MEMD;
        #pragma unroll 8
        for (int m = 0; m < MEMD; m++) acc += skr[m] * vwr[m];
        g_VK[bid * MEMD + tid] = acc;
    } else {
        for (int idx = tid; idx < OUTC * MEMD; idx += 128) {
            int c = idx >> 7, m = idx & 127;
            float v = 0.f;
            if (c < 128)      v = Ww[c * MEMD + m];
            else if (c < 148) v = sk[(c - 128) * MEMD + m];
            g_WK[idx] = v;
        }
        for (int idx = tid; idx < OUTC; idx += 128)
            g_BK[idx] = (idx < 128) ? Wb[idx] : 0.f;
    }
}

__global__ void k_gather(const int* __restrict__ ids, const float* __restrict__ E) {
    int idx = blockIdx.x * 256 + threadIdx.x;
    int row = idx >> 7, m = idx & 127;
    int b = row >> 7, t = row & 127;
    int tok = ids[b * 4096 + t];
    g_S[idx] = E[tok * MEMD + m];
}

__global__ void __launch_bounds__(256) k_gemm() {
    __shared__ float Ss[64][33];
    __shared__ float Ks[OUTC][33];
    int tid = threadIdx.x, row0 = blockIdx.x * 64;
    int tx = tid & 15, ty = tid >> 4;
    float acc[4][10];
    #pragma unroll
    for (int i = 0; i < 4; i++)
        #pragma unroll
        for (int j = 0; j < 10; j++) acc[i][j] = 0.f;
    for (int kk = 0; kk < 128; kk += 32) {
        #pragma unroll
        for (int i = 0; i < 8; i++) {
            int idx = tid + i * 256, r = idx >> 5, k = idx & 31;
            Ss[r][k] = g_S[(row0 + r) * 128 + kk + k];
        }
        #pragma unroll
        for (int i = 0; i < 20; i++) {
            int idx = tid + i * 256, c = idx >> 5, k = idx & 31;
            Ks[c][k] = g_WK[c * 128 + kk + k];
        }
        __syncthreads();
        #pragma unroll
        for (int k = 0; k < 32; k++) {
            float a[4], bv[10];
            #pragma unroll
            for (int i = 0; i < 4; i++)  a[i]  = Ss[ty * 4 + i][k];
            #pragma unroll
            for (int j = 0; j < 10; j++) bv[j] = Ks[tx * 10 + j][k];
            #pragma unroll
            for (int i = 0; i < 4; i++)
                #pragma unroll
                for (int j = 0; j < 10; j++) acc[i][j] = fmaf(a[i], bv[j], acc[i][j]);
        }
        __syncthreads();
    }
    #pragma unroll
    for (int i = 0; i < 4; i++)
        #pragma unroll
        for (int j = 0; j < 10; j++) {
            int r = row0 + ty * 4 + i, c = tx * 10 + j;
            g_O[r * OUTC + c] = acc[i][j] + g_BK[c];
        }
}

__global__ void __launch_bounds__(256, 1) k_main(const float* __restrict__ Uw,
                                                 const float* __restrict__ Ub) {
    __shared__ float mem_s[128 * 18];
    __shared__ float vk_s[HSLOT][128];
    __shared__ float s_s[128], ws_s[128];
    __shared__ float skey_s[HSLOT];
    __shared__ float g_sh[HSLOT];
    __shared__ float red_s[4][HSLOT];
    __shared__ float red2_s[4][HSLOT];
    __shared__ float inv_s[HSLOT];
    __shared__ unsigned long long comb[128][5];

    const int tid = threadIdx.x;
    const int n = tid & 127, mh = tid >> 7;
    const int cta = blockIdx.x;
    const int b = cta >> 1, half = cta & 1, slot0 = half * HSLOT;

    float uwr[64];
    {
        const float4* up = (const float4*)(Uw + n * 128 + mh * 64);
        #pragma unroll
        for (int i = 0; i < 16; i++) {
            float4 v = up[i];
            uwr[4*i] = v.x; uwr[4*i+1] = v.y; uwr[4*i+2] = v.z; uwr[4*i+3] = v.w;
        }
    }
    const float ubn = Ub[n];
    for (int idx = tid; idx < HSLOT * 128; idx += 256) {
        int j = idx >> 7, nn = idx & 127;
        vk_s[j][nn] = g_VK[(slot0 + j) * 128 + nn];
    }
    for (int idx = tid; idx < 128 * 18; idx += 256) mem_s[idx] = 0.f;

    float memv[10];
    #pragma unroll
    for (int j = 0; j < 10; j++) memv[j] = 0.f;

    unsigned gen = 0;
    if (tid == 0) gen = *(volatile unsigned*)&g_gen;
    __syncthreads();

    const float* Sb = g_S + (b * 128) * 128;
    const float* Ob = g_O + (b * 128) * OUTC;

    for (int t = 0; t < NSTEP; t++) {
        const int par = t & 1;
        if (mh == 0) {
            s_s[n]  = Sb[t * 128 + n];
            ws_s[n] = Ob[t * OUTC + n];
        } else if (n < HSLOT) {
            skey_s[n] = Ob[t * OUTC + 128 + slot0 + n];
        }
        __syncthreads();

        // gate
        if (mh == 0) {
            float sv = s_s[n];
            float p[10];
            #pragma unroll
            for (int j = 0; j < 10; j++) p[j] = sv * mem_s[n * 18 + j];
            #pragma unroll
            for (int j = 0; j < 10; j++) {
                p[j] += __shfl_xor_sync(0xffffffffu, p[j], 16);
                p[j] += __shfl_xor_sync(0xffffffffu, p[j], 8);
                p[j] += __shfl_xor_sync(0xffffffffu, p[j], 4);
                p[j] += __shfl_xor_sync(0xffffffffu, p[j], 2);
                p[j] += __shfl_xor_sync(0xffffffffu, p[j], 1);
            }
            if ((n & 31) == 0) {
                #pragma unroll
                for (int j = 0; j < 10; j++) red_s[n >> 5][j] = p[j];
            }
        }
        __syncthreads();
        if (tid < HSLOT) {
            float gs = red_s[0][tid] + red_s[1][tid] + red_s[2][tid] + red_s[3][tid]
                     + skey_s[tid];
            g_sh[tid] = 1.f / (1.f + expf(-gs));
        }

        // matmul h[j][n] = sum_m mem[m][j] * Uw[n][m], m split across halves
        unsigned long long accv[5];
        #pragma unroll
        for (int p = 0; p < 5; p++) accv[p] = 0ull;
        {
            const float* base = mem_s + mh * 64 * 18;
            #pragma unroll
            for (int k = 0; k < 64; k++) {
                unsigned long long u2 = pack2(uwr[k]);
                const unsigned long long* mp = (const unsigned long long*)(base + k * 18);
                ffma2(accv[0], u2, mp[0]);
                ffma2(accv[1], u2, mp[1]);
                ffma2(accv[2], u2, mp[2]);
                ffma2(accv[3], u2, mp[3]);
                ffma2(accv[4], u2, mp[4]);
            }
        }
        if (mh == 1) {
            #pragma unroll
            for (int p = 0; p < 5; p++) comb[n][p] = accv[p];
        }
        __syncthreads();

        if (mh == 0) {
            const float wsv = ws_s[n];
            float sq[10];
            #pragma unroll
            for (int p = 0; p < 5; p++) {
                float2 av = up2(accv[p]);
                float2 cv = up2(comb[n][p]);
                float h0 = fmaxf(av.x + cv.x + ubn + vk_s[2*p][n]   + wsv, 0.f);
                float h1 = fmaxf(av.y + cv.y + ubn + vk_s[2*p+1][n] + wsv, 0.f);
                memv[2*p]   = fmaf(g_sh[2*p],   h0, memv[2*p]);
                memv[2*p+1] = fmaf(g_sh[2*p+1], h1, memv[2*p+1]);
                sq[2*p]   = memv[2*p]   * memv[2*p];
                sq[2*p+1] = memv[2*p+1] * memv[2*p+1];
            }
            #pragma unroll
            for (int j = 0; j < 10; j++) {
                sq[j] += __shfl_xor_sync(0xffffffffu, sq[j], 16);
                sq[j] += __shfl_xor_sync(0xffffffffu, sq[j], 8);
                sq[j] += __shfl_xor_sync(0xffffffffu, sq[j], 4);
                sq[j] += __shfl_xor_sync(0xffffffffu, sq[j], 2);
                sq[j] += __shfl_xor_sync(0xffffffffu, sq[j], 1);
            }
            if ((n & 31) == 0) {
                #pragma unroll
                for (int j = 0; j < 10; j++) red2_s[n >> 5][j] = sq[j];
            }
        }
        __syncthreads();
        if (tid < HSLOT) {
            float ps = red2_s[0][tid] + red2_s[1][tid] + red2_s[2][tid] + red2_s[3][tid];
            *(volatile float*)&g_part[par][cta][tid] = ps;
        }
        __threadfence();
        __syncthreads();

        // grid barrier
        if (tid == 0) {
            unsigned arr = atomicAdd(&g_cnt, 1u);
            if (arr == NCTA - 1) {
                g_cnt = 0u;
                __threadfence();
                atomicAdd(&g_gen, 1u);
            } else {
                while (*(volatile unsigned*)&g_gen == gen) { }
            }
            gen++;
            __threadfence();
        }
        __syncthreads();

        // per-slot norm over all batches
        if (tid < 160) {
            int j = tid >> 4, i = tid & 15;
            float sm = 0.f;
            #pragma unroll
            for (int kk = 0; kk < 4; kk++)
                sm += *(volatile float*)&g_part[par][(i + 16*kk) * 2 + half][j];
            sm += __shfl_xor_sync(0xffffffffu, sm, 8);
            sm += __shfl_xor_sync(0xffffffffu, sm, 4);
            sm += __shfl_xor_sync(0xffffffffu, sm, 2);
            sm += __shfl_xor_sync(0xffffffffu, sm, 1);
            if (i == 0) inv_s[j] = 1.f / sqrtf(sm);
        }
        __syncthreads();

        if (mh == 0) {
            #pragma unroll
            for (int p = 0; p < 5; p++) {
                memv[2*p]   *= inv_s[2*p];
                memv[2*p+1] *= inv_s[2*p+1];
                *(float2*)&mem_s[n * 18 + 2*p] = make_float2(memv[2*p], memv[2*p+1]);
            }
        }
    }

    if (mh == 0) {
        #pragma unroll
        for (int j = 0; j < 10; j++)
            g_H[b * (NSLOT * MEMD) + (slot0 + j) * MEMD + n] = memv[j];
    }
}

__global__ void k_epi(const int* __restrict__ q, const int* __restrict__ ans,
                      const float* __restrict__ E, const float* __restrict__ Hw,
                      const float* __restrict__ Hb, float* __restrict__ out) {
    __shared__ float red[4][NSLOT];
    __shared__ float p_s[NSLOT];
    __shared__ float u_s[MEMD];
    __shared__ float yr[4][2];
    int b = blockIdx.x, n = threadIdx.x, w = n >> 5, l = n & 31;

    float qv = 0.f;
    #pragma unroll
    for (int i = 0; i < 16; i++) qv += E[q[b * 16 + i] * MEMD + n];
    qv *= (1.f / 16.f);
    float a1 = 0.f, a2 = 0.f;
    #pragma unroll
    for (int i = 0; i < 8; i++) {
        a1 += E[ans[(b * 8 + i) * 2 + 0] * MEMD + n];
        a2 += E[ans[(b * 8 + i) * 2 + 1] * MEMD + n];
    }
    a1 *= 0.125f; a2 *= 0.125f;

    float hv[NSLOT], p[NSLOT];
    #pragma unroll
    for (int j = 0; j < NSLOT; j++) {
        hv[j] = g_H[b * (NSLOT * MEMD) + j * MEMD + n];
        p[j] = hv[j] * qv;
    }
    #pragma unroll
    for (int j = 0; j < NSLOT; j++) {
        p[j] += __shfl_xor_sync(0xffffffffu, p[j], 16);
        p[j] += __shfl_xor_sync(0xffffffffu, p[j], 8);
        p[j] += __shfl_xor_sync(0xffffffffu, p[j], 4);
        p[j] += __shfl_xor_sync(0xffffffffu, p[j], 2);
        p[j] += __shfl_xor_sync(0xffffffffu, p[j], 1);
    }
    if (l == 0) {
        #pragma unroll
        for (int j = 0; j < NSLOT; j++) red[w][j] = p[j];
    }
    __syncthreads();
    if (n == 0) {
        float d[NSLOT], mx = -1e30f;
        #pragma unroll
        for (int j = 0; j < NSLOT; j++) {
            d[j] = red[0][j] + red[1][j] + red[2][j] + red[3][j];
            mx = fmaxf(mx, d[j]);
        }
        float sm = 0.f;
        #pragma unroll
        for (int j = 0; j < NSLOT; j++) { d[j] = expf(d[j] - mx); sm += d[j]; }
        float inv = 1.f / sm;
        #pragma unroll
        for (int j = 0; j < NSLOT; j++) p_s[j] = d[j] * inv;
    }
    __syncthreads();

    float u = 0.f;
    #pragma unroll
    for (int j = 0; j < NSLOT; j++) u = fmaf(p_s[j], hv[j], u);
    u_s[n] = u;
    __syncthreads();

    float r = qv + Hb[n];
    const float* hwr = Hw + n * MEMD;
    #pragma unroll 8
    for (int m = 0; m < MEMD; m++) r = fmaf(u_s[m], hwr[m], r);
    r = fmaxf(r, 0.f);

    float y1 = r * a1, y2 = r * a2;
    #pragma unroll
    for (int s = 16; s; s >>= 1) {
        y1 += __shfl_xor_sync(0xffffffffu, y1, s);
        y2 += __shfl_xor_sync(0xffffffffu, y2, s);
    }
    if (l == 0) { yr[w][0] = y1; yr[w][1] = y2; }
    __syncthreads();
    if (n == 0) {
        float s1 = yr[0][0] + yr[1][0] + yr[2][0] + yr[3][0];
        float s2 = yr[0][1] + yr[1][1] + yr[2][1] + yr[3][1];
        float mx = fmaxf(s1, s2);
        float e1 = expf(s1 - mx), e2 = expf(s2 - mx);
        float inv = 1.f / (e1 + e2);
        out[b * 2 + 0] = e1 * inv;
        out[b * 2 + 1] = e2 * inv;
    }
}

extern "C" void kernel_launch(void* const* d_in, const int* in_sizes, int n_in,
                              void* d_out, int out_size) {
    const int*   input_ids = (const int*)  d_in[0];
    const int*   question  = (const int*)  d_in[1];
    const int*   ans       = (const int*)  d_in[2];
    const float* E         = (const float*)d_in[3];
    const float* Uw        = (const float*)d_in[4];
    const float* Ub        = (const float*)d_in[5];
    const float* Vw        = (const float*)d_in[6];
    const float* Vb        = (const float*)d_in[7];
    const float* Ww        = (const float*)d_in[8];
    const float* Wb        = (const float*)d_in[9];
    const float* sk        = (const float*)d_in[10];
    const float* Hw        = (const float*)d_in[11];
    const float* Hb        = (const float*)d_in[12];
    float* out = (float*)d_out;

    k_setup <<<21, 128>>>(Ww, Wb, sk, Vw, Vb);
    k_gather<<<4096, 256>>>(input_ids, E);
    k_gemm  <<<128, 256>>>();
    k_main  <<<128, 256>>>(Uw, Ub);
    k_epi   <<<64, 128>>>(question, ans, E, Hw, Hb, out);
}